// round 10
// baseline (speedup 1.0000x reference)
#include <cuda_runtime.h>
#include <cuda_fp16.h>
#include <math.h>
#include <stdint.h>

// ---------------- problem dims ----------------
#define T_TOK 2048
#define H_DIM 1024
#define F_DIM 4096
#define E_NUM 8
#define CAP   2048

#define RT_CAP 128      // CAP/16
#define CT1    64       // H/16  : ffn1 A k-tiles
#define NT1    256      // F/16  : ffn1 B n-tiles
#define CT2    256      // F/16  : ffn2 A k-tiles
#define NT2    64       // H/16  : ffn2 B n-tiles

// ---------------- device scratch (fragment-packed: 16B/lane per 16x16 tile) ----------------
__device__ int   d_cnt[E_NUM];
__device__ int   d_tok[E_NUM * CAP];
__device__ float d_wt [E_NUM * CAP];
__device__ uint4 d_xg [(size_t)E_NUM * RT_CAP * CT1 * 32];   // 32 MB  A-frags for ffn1
__device__ uint4 d_w1f[(size_t)E_NUM * CT1 * NT1 * 32];      // 64 MB  B-frags for ffn1
__device__ uint4 d_w2f[(size_t)E_NUM * CT2 * NT2 * 32];      // 64 MB  B-frags for ffn2
__device__ uint4 d_hf [(size_t)E_NUM * RT_CAP * CT2 * 32];   // 128 MB A-frags for ffn2

// ---------------- helpers ----------------
__device__ __forceinline__ void mma16816(float c[4], const uint32_t a[4],
                                         uint32_t b0, uint32_t b1) {
    asm volatile(
        "mma.sync.aligned.m16n8k16.row.col.f32.f16.f16.f32 "
        "{%0,%1,%2,%3}, {%4,%5,%6,%7}, {%8,%9}, {%0,%1,%2,%3};\n"
        : "+f"(c[0]), "+f"(c[1]), "+f"(c[2]), "+f"(c[3])
        : "r"(a[0]), "r"(a[1]), "r"(a[2]), "r"(a[3]), "r"(b0), "r"(b1));
}
__device__ __forceinline__ uint32_t pk(float a, float b) {
    half2 h = __floats2half2_rn(a, b);
    return *(uint32_t*)&h;
}
__device__ __forceinline__ void ldg128(uint32_t r[4], const uint4* p) {
    uint4 v = __ldg(p);
    r[0] = v.x; r[1] = v.y; r[2] = v.z; r[3] = v.w;
}

// ---------------- kernel 0: zero counters (output zeroed by cudaMemsetAsync) --------
__global__ void moe_cnt_kernel() {
    if (threadIdx.x < E_NUM) d_cnt[threadIdx.x] = 0;
}

// ---------------- kernel 1: router (warp per token) ----------------
__global__ __launch_bounds__(256) void moe_router_kernel(
    const float* __restrict__ x, const float* __restrict__ gw, const float* __restrict__ gb)
{
    int t = blockIdx.x * 8 + (threadIdx.x >> 5);
    int lane = threadIdx.x & 31;
    if (t >= T_TOK) return;
    float s[E_NUM];
    #pragma unroll
    for (int e = 0; e < E_NUM; e++) s[e] = 0.f;
    #pragma unroll 4
    for (int j = 0; j < H_DIM / 32; j++) {
        float xv = x[(size_t)t * H_DIM + j * 32 + lane];
        const float4* g = (const float4*)(gw + (size_t)(j * 32 + lane) * E_NUM);
        float4 g0 = g[0], g1 = g[1];
        s[0] += xv * g0.x; s[1] += xv * g0.y; s[2] += xv * g0.z; s[3] += xv * g0.w;
        s[4] += xv * g1.x; s[5] += xv * g1.y; s[6] += xv * g1.z; s[7] += xv * g1.w;
    }
    #pragma unroll
    for (int e = 0; e < E_NUM; e++) {
        #pragma unroll
        for (int o = 16; o; o >>= 1) s[e] += __shfl_xor_sync(0xffffffffu, s[e], o);
    }
    if (lane == 0) {
        float lg[E_NUM];
        #pragma unroll
        for (int e = 0; e < E_NUM; e++) lg[e] = s[e] + gb[e];
        int i1 = 0; float l1 = lg[0];
        #pragma unroll
        for (int e = 1; e < E_NUM; e++) if (lg[e] > l1) { l1 = lg[e]; i1 = e; }
        int i2 = -1; float l2 = -1e30f;
        #pragma unroll
        for (int e = 0; e < E_NUM; e++) if (e != i1 && lg[e] > l2) { l2 = lg[e]; i2 = e; }
        float p1 = 1.0f / (1.0f + expf(l2 - l1));
        float p2 = 1.0f - p1;
        int q1 = atomicAdd(&d_cnt[i1], 1);
        d_tok[i1 * CAP + q1] = t;  d_wt[i1 * CAP + q1] = p1;
        int q2 = atomicAdd(&d_cnt[i2], 1);
        d_tok[i2 * CAP + q2] = t;  d_wt[i2 * CAP + q2] = p2;
    }
}

// ---------------- kernel 2: gather x rows into A-fragments (zero-padded) ----------------
__global__ __launch_bounds__(128) void moe_xgather_kernel(const float* __restrict__ x) {
    int e  = blockIdx.y;
    int rt = blockIdx.x;
    int M  = d_cnt[e];
    int Mceil = (M + 127) & ~127;
    if (rt * 16 >= Mceil) return;
    int w = threadIdx.x >> 5, lane = threadIdx.x & 31;
    int grp = lane >> 2, t4 = lane & 3;
    int r0 = rt * 16 + grp, r8 = r0 + 8;
    bool v0 = r0 < M, v8 = r8 < M;
    const float* x0 = x + (size_t)(v0 ? d_tok[e * CAP + r0] : 0) * H_DIM;
    const float* x8 = x + (size_t)(v8 ? d_tok[e * CAP + r8] : 0) * H_DIM;
    uint4* dst = d_xg + ((size_t)(e * RT_CAP + rt) * CT1) * 32 + lane;
    for (int ct = w; ct < CT1; ct += 4) {
        int c = ct * 16 + 2 * t4;
        float2 z = make_float2(0.f, 0.f);
        float2 lo0 = v0 ? *(const float2*)(x0 + c)     : z;
        float2 lo8 = v8 ? *(const float2*)(x8 + c)     : z;
        float2 hi0 = v0 ? *(const float2*)(x0 + c + 8) : z;
        float2 hi8 = v8 ? *(const float2*)(x8 + c + 8) : z;
        uint4 o;
        o.x = pk(lo0.x, lo0.y);
        o.y = pk(lo8.x, lo8.y);
        o.z = pk(hi0.x, hi0.y);
        o.w = pk(hi8.x, hi8.y);
        dst[(size_t)ct * 32] = o;
    }
}

// ---------------- kernel 3: pack BOTH weight tensors -> B-fragments (one launch) ------
// grid (64, 16, 16): z<8 -> w1 expert z ; z>=8 -> w2 expert z-8 (x/y roles swapped)
__global__ __launch_bounds__(256) void moe_wpack_kernel(
    const float* __restrict__ w1, const float* __restrict__ w2)
{
    __shared__ float sm[64][68];
    int which = blockIdx.z >> 3;
    int e     = blockIdx.z & 7;
    const float* W; uint4* out; int K, N, nb, kb;
    if (!which) { W = w1; out = d_w1f; K = H_DIM; N = F_DIM; nb = blockIdx.x; kb = blockIdx.y; }
    else        { W = w2; out = d_w2f; K = F_DIM; N = H_DIM; nb = blockIdx.y; kb = blockIdx.x; }
    int tid = threadIdx.x;
    int k0 = kb * 64, n0 = nb * 64;
    const float* Wb = W + (size_t)e * K * N;
    #pragma unroll
    for (int it = 0; it < 4; it++) {
        int row = it * 16 + (tid >> 4);
        int col = (tid & 15) * 4;
        float4 v = *(const float4*)(Wb + (size_t)(k0 + row) * N + n0 + col);
        sm[row][col] = v.x; sm[row][col + 1] = v.y;
        sm[row][col + 2] = v.z; sm[row][col + 3] = v.w;
    }
    __syncthreads();
    int w = tid >> 5, lane = tid & 31;
    int grp = lane >> 2, t4 = lane & 3;
    int KT = K >> 4, NT = N >> 4;
    #pragma unroll
    for (int id = w; id < 16; id += 8) {
        int tk = id >> 2, tn = id & 3;
        int kbb = tk * 16 + 2 * t4, nl = tn * 16 + grp, nh = nl + 8;
        uint4 o;
        o.x = pk(sm[kbb][nl],     sm[kbb + 1][nl]);
        o.y = pk(sm[kbb + 8][nl], sm[kbb + 9][nl]);
        o.z = pk(sm[kbb][nh],     sm[kbb + 1][nh]);
        o.w = pk(sm[kbb + 8][nh], sm[kbb + 9][nh]);
        out[(((size_t)e * KT + kb * 4 + tk) * NT + nb * 4 + tn) * 32 + lane] = o;
    }
}

// ================= fragment GEMM mainloop: distance-2, 3-buffer pipeline ==============
#define LOADF(AF, BF, ss)                                                    \
    do {                                                                     \
        _Pragma("unroll")                                                    \
        for (int mi = 0; mi < 4; mi++) ldg128(AF[mi], aP[mi] + (size_t)(ss) * 32); \
        _Pragma("unroll")                                                    \
        for (int j = 0; j < 4; j++)                                          \
            ldg128(BF[j], bP + (size_t)(ss) * (BNT) * 32 + j * 32);          \
    } while (0)

#define MMAF(AF, BF)                                                         \
    do {                                                                     \
        _Pragma("unroll")                                                    \
        for (int j = 0; j < 4; j++)                                          \
            _Pragma("unroll")                                                \
            for (int mi = 0; mi < 4; mi++) {                                 \
                mma16816(acc[mi][2 * j],     AF[mi], BF[j][0], BF[j][1]);    \
                mma16816(acc[mi][2 * j + 1], AF[mi], BF[j][2], BF[j][3]);    \
            }                                                                \
    } while (0)

#define GEMM_MAIN(NS_, ABASE, BBASE, BNT_)                                   \
    const int NS = (NS_);                                                    \
    const int BNT = (BNT_);                                                  \
    int tid = threadIdx.x, warp = tid >> 5, lane = tid & 31;                 \
    int wm = warp >> 1, wn = warp & 1;                                       \
    int grp = lane >> 2, t4 = lane & 3;                                      \
    int rt0 = (m0 >> 4) + wm * 4, nt0 = (n0 >> 4) + wn * 4;                  \
    const uint4* aP[4];                                                      \
    _Pragma("unroll")                                                        \
    for (int mi = 0; mi < 4; mi++)                                           \
        aP[mi] = (ABASE) + ((size_t)(rt0 + mi) * NS) * 32 + lane;            \
    const uint4* bP = (BBASE) + (size_t)nt0 * 32 + lane;                     \
    float acc[4][8][4];                                                      \
    _Pragma("unroll")                                                        \
    for (int mi = 0; mi < 4; mi++)                                           \
        _Pragma("unroll")                                                    \
        for (int ni = 0; ni < 8; ni++)                                       \
            _Pragma("unroll")                                                \
            for (int q = 0; q < 4; q++) acc[mi][ni][q] = 0.f;                \
    uint32_t aF[3][4][4], bF[3][4][4];                                       \
    LOADF(aF[0], bF[0], 0);                                                  \
    LOADF(aF[1], bF[1], 1);                                                  \
    _Pragma("unroll 1")                                                      \
    for (int s = 0; s < NS; s += 3) {                                        \
        int i2 = (s + 2 < NS) ? s + 2 : NS - 1;                              \
        int i3 = (s + 3 < NS) ? s + 3 : NS - 1;                              \
        int i4 = (s + 4 < NS) ? s + 4 : NS - 1;                              \
        LOADF(aF[2], bF[2], i2);                                             \
        MMAF(aF[0], bF[0]);                                                  \
        LOADF(aF[0], bF[0], i3);                                             \
        if (s + 1 < NS) MMAF(aF[1], bF[1]);                                  \
        LOADF(aF[1], bF[1], i4);                                             \
        if (s + 2 < NS) MMAF(aF[2], bF[2]);                                  \
    }

// ---------------- kernel 4: GEMM1  h = relu(Xg @ W1[e] + b1) -> h fragments ----------------
__global__ __launch_bounds__(128, 2) void moe_ffn1_kernel(const float* __restrict__ b1)
{
    int e  = blockIdx.z;
    int M  = d_cnt[e];
    int m0 = blockIdx.y * 128;
    if (m0 >= M) return;
    int n0 = blockIdx.x * 128;

    GEMM_MAIN(CT1,
              d_xg  + (size_t)e * RT_CAP * CT1 * 32,
              d_w1f + (size_t)e * CT1 * NT1 * 32,
              NT1)

    // epilogue: relu(acc + b1) packed directly as ffn2 A-fragments
    const float* bb = b1 + (size_t)e * F_DIM + n0 + wn * 64;
    #pragma unroll
    for (int mi = 0; mi < 4; mi++) {
        size_t rbase = ((size_t)(e * RT_CAP) + (rt0 + mi)) * CT2;
        #pragma unroll
        for (int j = 0; j < 4; j++) {
            float2 blo = *(const float2*)(bb + j * 16 + 2 * t4);
            float2 bhi = *(const float2*)(bb + j * 16 + 8 + 2 * t4);
            uint4 o;
            o.x = pk(fmaxf(acc[mi][2*j][0]   + blo.x, 0.f), fmaxf(acc[mi][2*j][1]   + blo.y, 0.f));
            o.y = pk(fmaxf(acc[mi][2*j][2]   + blo.x, 0.f), fmaxf(acc[mi][2*j][3]   + blo.y, 0.f));
            o.z = pk(fmaxf(acc[mi][2*j+1][0] + bhi.x, 0.f), fmaxf(acc[mi][2*j+1][1] + bhi.y, 0.f));
            o.w = pk(fmaxf(acc[mi][2*j+1][2] + bhi.x, 0.f), fmaxf(acc[mi][2*j+1][3] + bhi.y, 0.f));
            d_hf[(rbase + nt0 + j) * 32 + lane] = o;
        }
    }
}

// ---------------- kernel 5: GEMM2  out[tok] += wt*(h @ W2[e] + b2) ----------------
__global__ __launch_bounds__(128, 2) void moe_ffn2_kernel(const float* __restrict__ b2,
                                                          float* __restrict__ out)
{
    int e  = blockIdx.z;
    int M  = d_cnt[e];
    int m0 = blockIdx.y * 128;
    if (m0 >= M) return;
    int n0 = blockIdx.x * 128;

    GEMM_MAIN(CT2,
              d_hf  + (size_t)e * RT_CAP * CT2 * 32,
              d_w2f + (size_t)e * CT2 * NT2 * 32,
              NT2)

    // epilogue: scatter wt*(acc + b2) into out (2 atomic adds per out element total)
    #pragma unroll
    for (int mi = 0; mi < 4; mi++) {
        int r = m0 + wm * 64 + mi * 16 + grp;
        bool v0 = (r < M), v1 = (r + 8 < M);
        int tok0 = 0, tok1 = 0; float wt0 = 0.f, wt1 = 0.f;
        if (v0) { tok0 = d_tok[e * CAP + r];     wt0 = d_wt[e * CAP + r]; }
        if (v1) { tok1 = d_tok[e * CAP + r + 8]; wt1 = d_wt[e * CAP + r + 8]; }
        #pragma unroll
        for (int ni = 0; ni < 8; ni++) {
            int c = n0 + wn * 64 + ni * 8 + t4 * 2;
            float2 bv = *(const float2*)(b2 + (size_t)e * H_DIM + c);
            if (v0) {
                atomicAdd(out + (size_t)tok0 * H_DIM + c,     wt0 * (acc[mi][ni][0] + bv.x));
                atomicAdd(out + (size_t)tok0 * H_DIM + c + 1, wt0 * (acc[mi][ni][1] + bv.y));
            }
            if (v1) {
                atomicAdd(out + (size_t)tok1 * H_DIM + c,     wt1 * (acc[mi][ni][2] + bv.x));
                atomicAdd(out + (size_t)tok1 * H_DIM + c + 1, wt1 * (acc[mi][ni][3] + bv.y));
            }
        }
    }
}

// ---------------- launch ----------------
extern "C" void kernel_launch(void* const* d_in, const int* in_sizes, int n_in,
                              void* d_out, int out_size) {
    const float* x  = (const float*)d_in[0];
    const float* gw = (const float*)d_in[1];
    const float* gb = (const float*)d_in[2];
    const float* w1 = (const float*)d_in[3];
    const float* b1 = (const float*)d_in[4];
    const float* w2 = (const float*)d_in[5];
    const float* b2 = (const float*)d_in[6];
    float* out = (float*)d_out;

    cudaMemsetAsync(out, 0, (size_t)T_TOK * H_DIM * sizeof(float));
    moe_cnt_kernel<<<1, 32>>>();
    moe_router_kernel<<<T_TOK / 8, 256>>>(x, gw, gb);
    moe_xgather_kernel<<<dim3(RT_CAP, E_NUM), 128>>>(x);
    moe_wpack_kernel<<<dim3(64, 16, 16), 256>>>(w1, w2);
    moe_ffn1_kernel<<<dim3(F_DIM / 128, CAP / 128, E_NUM), 128>>>(b1);
    moe_ffn2_kernel<<<dim3(H_DIM / 128, CAP / 128, E_NUM), 128>>>(b2, out);
}

// round 11
// speedup vs baseline: 1.0828x; 1.0828x over previous
#include <cuda_runtime.h>
#include <cuda_fp16.h>
#include <math.h>
#include <stdint.h>

// ---------------- problem dims ----------------
#define T_TOK 2048
#define H_DIM 1024
#define F_DIM 4096
#define E_NUM 8
#define CAP   2048

#define RT_CAP 128      // CAP/16
#define CT1    64       // H/16  : ffn1 A k-tiles
#define NT1    256      // F/16  : ffn1 B n-tiles
#define CT2    256      // F/16  : ffn2 A k-tiles
#define NT2    64       // H/16  : ffn2 B n-tiles

// ---------------- device scratch (fragment-packed: 16B/lane per 16x16 tile) ----------------
__device__ int   d_cnt[E_NUM];
__device__ int   d_tok[E_NUM * CAP];
__device__ float d_wt [E_NUM * CAP];
__device__ uint4 d_xg [(size_t)E_NUM * RT_CAP * CT1 * 32];   // 32 MB  A-frags for ffn1
__device__ uint4 d_w1f[(size_t)E_NUM * CT1 * NT1 * 32];      // 64 MB  B-frags for ffn1
__device__ uint4 d_w2f[(size_t)E_NUM * CT2 * NT2 * 32];      // 64 MB  B-frags for ffn2
__device__ uint4 d_hf [(size_t)E_NUM * RT_CAP * CT2 * 32];   // 128 MB A-frags for ffn2

// ---------------- helpers ----------------
__device__ __forceinline__ void mma16816(float c[4], const uint32_t a[4],
                                         uint32_t b0, uint32_t b1) {
    asm volatile(
        "mma.sync.aligned.m16n8k16.row.col.f32.f16.f16.f32 "
        "{%0,%1,%2,%3}, {%4,%5,%6,%7}, {%8,%9}, {%0,%1,%2,%3};\n"
        : "+f"(c[0]), "+f"(c[1]), "+f"(c[2]), "+f"(c[3])
        : "r"(a[0]), "r"(a[1]), "r"(a[2]), "r"(a[3]), "r"(b0), "r"(b1));
}
__device__ __forceinline__ uint32_t pk(float a, float b) {
    half2 h = __floats2half2_rn(a, b);
    return *(uint32_t*)&h;
}
__device__ __forceinline__ void ldg128(uint32_t r[4], const uint4* p) {
    uint4 v = __ldg(p);
    r[0] = v.x; r[1] = v.y; r[2] = v.z; r[3] = v.w;
}

// ---------------- kernel 0: zero counters (output zeroed by cudaMemsetAsync) --------
__global__ void moe_cnt_kernel() {
    if (threadIdx.x < E_NUM) d_cnt[threadIdx.x] = 0;
}

// ---------------- kernel 1: router (warp per token) ----------------
__global__ __launch_bounds__(256) void moe_router_kernel(
    const float* __restrict__ x, const float* __restrict__ gw, const float* __restrict__ gb)
{
    int t = blockIdx.x * 8 + (threadIdx.x >> 5);
    int lane = threadIdx.x & 31;
    if (t >= T_TOK) return;
    float s[E_NUM];
    #pragma unroll
    for (int e = 0; e < E_NUM; e++) s[e] = 0.f;
    #pragma unroll 4
    for (int j = 0; j < H_DIM / 32; j++) {
        float xv = x[(size_t)t * H_DIM + j * 32 + lane];
        const float4* g = (const float4*)(gw + (size_t)(j * 32 + lane) * E_NUM);
        float4 g0 = g[0], g1 = g[1];
        s[0] += xv * g0.x; s[1] += xv * g0.y; s[2] += xv * g0.z; s[3] += xv * g0.w;
        s[4] += xv * g1.x; s[5] += xv * g1.y; s[6] += xv * g1.z; s[7] += xv * g1.w;
    }
    #pragma unroll
    for (int e = 0; e < E_NUM; e++) {
        #pragma unroll
        for (int o = 16; o; o >>= 1) s[e] += __shfl_xor_sync(0xffffffffu, s[e], o);
    }
    if (lane == 0) {
        float lg[E_NUM];
        #pragma unroll
        for (int e = 0; e < E_NUM; e++) lg[e] = s[e] + gb[e];
        int i1 = 0; float l1 = lg[0];
        #pragma unroll
        for (int e = 1; e < E_NUM; e++) if (lg[e] > l1) { l1 = lg[e]; i1 = e; }
        int i2 = -1; float l2 = -1e30f;
        #pragma unroll
        for (int e = 0; e < E_NUM; e++) if (e != i1 && lg[e] > l2) { l2 = lg[e]; i2 = e; }
        float p1 = 1.0f / (1.0f + expf(l2 - l1));
        float p2 = 1.0f - p1;
        int q1 = atomicAdd(&d_cnt[i1], 1);
        d_tok[i1 * CAP + q1] = t;  d_wt[i1 * CAP + q1] = p1;
        int q2 = atomicAdd(&d_cnt[i2], 1);
        d_tok[i2 * CAP + q2] = t;  d_wt[i2 * CAP + q2] = p2;
    }
}

// ---------------- kernel 2: gather x rows into A-fragments (zero-padded) ----------------
__global__ __launch_bounds__(128) void moe_xgather_kernel(const float* __restrict__ x) {
    int e  = blockIdx.y;
    int rt = blockIdx.x;
    int M  = d_cnt[e];
    int Mceil = (M + 127) & ~127;
    if (rt * 16 >= Mceil) return;
    int w = threadIdx.x >> 5, lane = threadIdx.x & 31;
    int grp = lane >> 2, t4 = lane & 3;
    int r0 = rt * 16 + grp, r8 = r0 + 8;
    bool v0 = r0 < M, v8 = r8 < M;
    const float* x0 = x + (size_t)(v0 ? d_tok[e * CAP + r0] : 0) * H_DIM;
    const float* x8 = x + (size_t)(v8 ? d_tok[e * CAP + r8] : 0) * H_DIM;
    uint4* dst = d_xg + ((size_t)(e * RT_CAP + rt) * CT1) * 32 + lane;
    for (int ct = w; ct < CT1; ct += 4) {
        int c = ct * 16 + 2 * t4;
        float2 z = make_float2(0.f, 0.f);
        float2 lo0 = v0 ? *(const float2*)(x0 + c)     : z;
        float2 lo8 = v8 ? *(const float2*)(x8 + c)     : z;
        float2 hi0 = v0 ? *(const float2*)(x0 + c + 8) : z;
        float2 hi8 = v8 ? *(const float2*)(x8 + c + 8) : z;
        uint4 o;
        o.x = pk(lo0.x, lo0.y);
        o.y = pk(lo8.x, lo8.y);
        o.z = pk(hi0.x, hi0.y);
        o.w = pk(hi8.x, hi8.y);
        dst[(size_t)ct * 32] = o;
    }
}

// ---------------- kernel 3: pack weights [K][N] f32 -> B-fragments f16 ----------------
// which=0 -> d_w1f, which=1 -> d_w2f  (destination resolved in device code)
__global__ __launch_bounds__(256) void moe_wpack_kernel(
    const float* __restrict__ W, int which, int K, int N)
{
    __shared__ float sm[64][68];
    uint4* out = which ? d_w2f : d_w1f;
    int tid = threadIdx.x;
    int k0 = blockIdx.y * 64, n0 = blockIdx.x * 64;
    const float* Wb = W + (size_t)blockIdx.z * K * N;
    #pragma unroll
    for (int it = 0; it < 4; it++) {
        int row = it * 16 + (tid >> 4);
        int col = (tid & 15) * 4;
        float4 v = *(const float4*)(Wb + (size_t)(k0 + row) * N + n0 + col);
        sm[row][col] = v.x; sm[row][col + 1] = v.y;
        sm[row][col + 2] = v.z; sm[row][col + 3] = v.w;
    }
    __syncthreads();
    int w = tid >> 5, lane = tid & 31;
    int grp = lane >> 2, t4 = lane & 3;
    int KT = K >> 4, NT = N >> 4;
    #pragma unroll
    for (int id = w; id < 16; id += 8) {
        int tk = id >> 2, tn = id & 3;
        int kb = tk * 16 + 2 * t4, nl = tn * 16 + grp, nh = nl + 8;
        uint4 o;
        o.x = pk(sm[kb][nl],     sm[kb + 1][nl]);
        o.y = pk(sm[kb + 8][nl], sm[kb + 9][nl]);
        o.z = pk(sm[kb][nh],     sm[kb + 1][nh]);
        o.w = pk(sm[kb + 8][nh], sm[kb + 9][nh]);
        out[(((size_t)blockIdx.z * KT + blockIdx.y * 4 + tk) * NT
             + blockIdx.x * 4 + tn) * 32 + lane] = o;
    }
}

// ================= fragment GEMM mainloop (R9 distance-1, measured best) =============
#define LOADF(AF, BF, ss)                                                    \
    do {                                                                     \
        _Pragma("unroll")                                                    \
        for (int mi = 0; mi < 4; mi++) ldg128(AF[mi], aP[mi] + (size_t)(ss) * 32); \
        _Pragma("unroll")                                                    \
        for (int j = 0; j < 4; j++)                                          \
            ldg128(BF[j], bP + (size_t)(ss) * (BNT) * 32 + j * 32);          \
    } while (0)

#define MMAF(AF, BF)                                                         \
    do {                                                                     \
        _Pragma("unroll")                                                    \
        for (int j = 0; j < 4; j++)                                          \
            _Pragma("unroll")                                                \
            for (int mi = 0; mi < 4; mi++) {                                 \
                mma16816(acc[mi][2 * j],     AF[mi], BF[j][0], BF[j][1]);    \
                mma16816(acc[mi][2 * j + 1], AF[mi], BF[j][2], BF[j][3]);    \
            }                                                                \
    } while (0)

#define GEMM_MAIN(NS_, ABASE, BBASE, BNT_)                                   \
    const int NS = (NS_);                                                    \
    const int BNT = (BNT_);                                                  \
    int tid = threadIdx.x, warp = tid >> 5, lane = tid & 31;                 \
    int wm = warp >> 1, wn = warp & 1;                                       \
    int grp = lane >> 2, t4 = lane & 3;                                      \
    int rt0 = (m0 >> 4) + wm * 4, nt0 = (n0 >> 4) + wn * 4;                  \
    const uint4* aP[4];                                                      \
    _Pragma("unroll")                                                        \
    for (int mi = 0; mi < 4; mi++)                                           \
        aP[mi] = (ABASE) + ((size_t)(rt0 + mi) * NS) * 32 + lane;            \
    const uint4* bP = (BBASE) + (size_t)nt0 * 32 + lane;                     \
    float acc[4][8][4];                                                      \
    _Pragma("unroll")                                                        \
    for (int mi = 0; mi < 4; mi++)                                           \
        _Pragma("unroll")                                                    \
        for (int ni = 0; ni < 8; ni++)                                       \
            _Pragma("unroll")                                                \
            for (int q = 0; q < 4; q++) acc[mi][ni][q] = 0.f;                \
    uint32_t aF0[4][4], bF0[4][4], aF1[4][4], bF1[4][4];                     \
    LOADF(aF0, bF0, 0);                                                      \
    for (int s = 0; s < NS; s += 2) {                                        \
        LOADF(aF1, bF1, s + 1);                                              \
        MMAF(aF0, bF0);                                                      \
        if (s + 2 < NS) LOADF(aF0, bF0, s + 2);                              \
        MMAF(aF1, bF1);                                                      \
    }

// ---------------- kernel 4: GEMM1  h = relu(Xg @ W1[e] + b1) -> h fragments ----------------
__global__ __launch_bounds__(128, 2) void moe_ffn1_kernel(const float* __restrict__ b1)
{
    int e  = blockIdx.z;
    int M  = d_cnt[e];
    int m0 = blockIdx.y * 128;
    if (m0 >= M) return;
    int n0 = blockIdx.x * 128;

    GEMM_MAIN(CT1,
              d_xg  + (size_t)e * RT_CAP * CT1 * 32,
              d_w1f + (size_t)e * CT1 * NT1 * 32,
              NT1)

    // epilogue: relu(acc + b1) packed directly as ffn2 A-fragments
    const float* bb = b1 + (size_t)e * F_DIM + n0 + wn * 64;
    #pragma unroll
    for (int mi = 0; mi < 4; mi++) {
        size_t rbase = ((size_t)(e * RT_CAP) + (rt0 + mi)) * CT2;
        #pragma unroll
        for (int j = 0; j < 4; j++) {
            float2 blo = *(const float2*)(bb + j * 16 + 2 * t4);
            float2 bhi = *(const float2*)(bb + j * 16 + 8 + 2 * t4);
            uint4 o;
            o.x = pk(fmaxf(acc[mi][2*j][0]   + blo.x, 0.f), fmaxf(acc[mi][2*j][1]   + blo.y, 0.f));
            o.y = pk(fmaxf(acc[mi][2*j][2]   + blo.x, 0.f), fmaxf(acc[mi][2*j][3]   + blo.y, 0.f));
            o.z = pk(fmaxf(acc[mi][2*j+1][0] + bhi.x, 0.f), fmaxf(acc[mi][2*j+1][1] + bhi.y, 0.f));
            o.w = pk(fmaxf(acc[mi][2*j+1][2] + bhi.x, 0.f), fmaxf(acc[mi][2*j+1][3] + bhi.y, 0.f));
            d_hf[(rbase + nt0 + j) * 32 + lane] = o;
        }
    }
}

// ---------------- kernel 5: GEMM2  out[tok] += wt*(h @ W2[e] + b2) ----------------
__global__ __launch_bounds__(128, 2) void moe_ffn2_kernel(const float* __restrict__ b2,
                                                          float* __restrict__ out)
{
    int e  = blockIdx.z;
    int M  = d_cnt[e];
    int m0 = blockIdx.y * 128;
    if (m0 >= M) return;
    int n0 = blockIdx.x * 128;

    GEMM_MAIN(CT2,
              d_hf  + (size_t)e * RT_CAP * CT2 * 32,
              d_w2f + (size_t)e * CT2 * NT2 * 32,
              NT2)

    // epilogue: scatter wt*(acc + b2) into out (2 atomic adds per out element total)
    #pragma unroll
    for (int mi = 0; mi < 4; mi++) {
        int r = m0 + wm * 64 + mi * 16 + grp;
        bool v0 = (r < M), v1 = (r + 8 < M);
        int tok0 = 0, tok1 = 0; float wt0 = 0.f, wt1 = 0.f;
        if (v0) { tok0 = d_tok[e * CAP + r];     wt0 = d_wt[e * CAP + r]; }
        if (v1) { tok1 = d_tok[e * CAP + r + 8]; wt1 = d_wt[e * CAP + r + 8]; }
        #pragma unroll
        for (int ni = 0; ni < 8; ni++) {
            int c = n0 + wn * 64 + ni * 8 + t4 * 2;
            float2 bv = *(const float2*)(b2 + (size_t)e * H_DIM + c);
            if (v0) {
                atomicAdd(out + (size_t)tok0 * H_DIM + c,     wt0 * (acc[mi][ni][0] + bv.x));
                atomicAdd(out + (size_t)tok0 * H_DIM + c + 1, wt0 * (acc[mi][ni][1] + bv.y));
            }
            if (v1) {
                atomicAdd(out + (size_t)tok1 * H_DIM + c,     wt1 * (acc[mi][ni][2] + bv.x));
                atomicAdd(out + (size_t)tok1 * H_DIM + c + 1, wt1 * (acc[mi][ni][3] + bv.y));
            }
        }
    }
}

// ---------------- launch: dual-stream fork/join (capture-safe) ----------------
extern "C" void kernel_launch(void* const* d_in, const int* in_sizes, int n_in,
                              void* d_out, int out_size) {
    const float* x  = (const float*)d_in[0];
    const float* gw = (const float*)d_in[1];
    const float* gb = (const float*)d_in[2];
    const float* w1 = (const float*)d_in[3];
    const float* b1 = (const float*)d_in[4];
    const float* w2 = (const float*)d_in[5];
    const float* b2 = (const float*)d_in[6];
    float* out = (float*)d_out;

    // host-side objects (not device memory); created per call, not destroyed:
    // destroying a stream referenced by an in-progress capture invalidates it.
    cudaStream_t s2;
    cudaStreamCreateWithFlags(&s2, cudaStreamNonBlocking);
    cudaEvent_t evRoot, evW1, evW2;
    cudaEventCreateWithFlags(&evRoot, cudaEventDisableTiming);
    cudaEventCreateWithFlags(&evW1,   cudaEventDisableTiming);
    cudaEventCreateWithFlags(&evW2,   cudaEventDisableTiming);

    cudaMemsetAsync(out, 0, (size_t)T_TOK * H_DIM * sizeof(float));
    moe_cnt_kernel<<<1, 32>>>();

    // fork: weight packing runs on s2, concurrent with router/gather on s0
    cudaEventRecord(evRoot, 0);
    cudaStreamWaitEvent(s2, evRoot, 0);
    moe_wpack_kernel<<<dim3(F_DIM / 64, H_DIM / 64, E_NUM), 256, 0, s2>>>(w1, 0, H_DIM, F_DIM);
    cudaEventRecord(evW1, s2);
    moe_wpack_kernel<<<dim3(H_DIM / 64, F_DIM / 64, E_NUM), 256, 0, s2>>>(w2, 1, F_DIM, H_DIM);
    cudaEventRecord(evW2, s2);

    moe_router_kernel<<<T_TOK / 8, 256>>>(x, gw, gb);
    moe_xgather_kernel<<<dim3(RT_CAP, E_NUM), 128>>>(x);

    // join: ffn1 needs w1 fragments; ffn2 needs w2 fragments (w2pack hides under ffn1)
    cudaStreamWaitEvent(0, evW1, 0);
    moe_ffn1_kernel<<<dim3(F_DIM / 128, CAP / 128, E_NUM), 128>>>(b1);
    cudaStreamWaitEvent(0, evW2, 0);
    moe_ffn2_kernel<<<dim3(H_DIM / 128, CAP / 128, E_NUM), 128>>>(b2, out);
}